// round 15
// baseline (speedup 1.0000x reference)
#include <cuda_runtime.h>
#include <cuda_fp16.h>
#include <math.h>
#include <cstdint>

// Problem dims
#define T_  4
#define B_  32
#define C_  256
#define N_  1024     // H*W
#define EPS_ 1e-5f
#define NBATCH (T_ * B_)   // 128

#define SC_DOWN 4.8828125e-4f   // 2^-11, exact

// Scratch (allocation-free rule: __device__ globals)
__device__ float g_qlin[NBATCH * C_ * N_];                  // also reused as plin
__device__ float g_klin[NBATCH * C_ * N_];
__device__ __half g_xsplit[(size_t)NBATCH * 2 * N_ * C_];   // [batch][part][n][c]
__device__ __half g_xoneT[(size_t)NBATCH * N_ * C_];        // [batch][n][c]
__device__ __half g_wsplit[3 * 2 * C_ * C_];                // [branch(q,k,p)][part][o][c]

// ---------------- PTX helpers (family-agnostic, sm_80+) ----------------
__device__ __forceinline__ uint32_t smem_u32(const void* p) {
    uint32_t a;
    asm("{ .reg .u64 t; cvta.to.shared.u64 t, %1; cvt.u32.u64 %0, t; }" : "=r"(a) : "l"(p));
    return a;
}
__device__ __forceinline__ void ldsm_x4(uint32_t& r0, uint32_t& r1, uint32_t& r2,
                                        uint32_t& r3, uint32_t addr) {
    asm volatile("ldmatrix.sync.aligned.m8n8.x4.shared.b16 {%0,%1,%2,%3}, [%4];"
                 : "=r"(r0), "=r"(r1), "=r"(r2), "=r"(r3) : "r"(addr));
}
__device__ __forceinline__ void mma_fp16(float* d, const uint32_t* a, const uint32_t* b) {
    asm volatile("mma.sync.aligned.m16n8k16.row.col.f32.f16.f16.f32 "
                 "{%0,%1,%2,%3}, {%4,%5,%6,%7}, {%8,%9}, {%0,%1,%2,%3};"
                 : "+f"(d[0]), "+f"(d[1]), "+f"(d[2]), "+f"(d[3])
                 : "r"(a[0]), "r"(a[1]), "r"(a[2]), "r"(a[3]), "r"(b[0]), "r"(b[1]));
}
__device__ __forceinline__ void cpa16(uint32_t saddr, const void* g) {
    asm volatile("cp.async.cg.shared.global [%0], [%1], 16;" :: "r"(saddr), "l"(g) : "memory");
}
#define CP_COMMIT() asm volatile("cp.async.commit_group;" ::: "memory")
#define CP_WAIT0()  asm volatile("cp.async.wait_group 0;" ::: "memory")

// ---------------------------------------------------------------------------
// Split: fp32 -> 2x fp16, second limb pre-scaled by 2^11 (exact) so both
// limbs live in fp16 normal range. x = h1 + 2^-11 * h2s  (+ O(2^-22 x)).
// ---------------------------------------------------------------------------
__device__ __forceinline__ void split2(float v, __half& h1, __half& h2s) {
    h1 = __float2half_rn(v);
    float r = v - __half2float(h1);        // Sterbenz-exact
    h2s = __float2half_rn(r * 2048.0f);    // exact scaling
}

__global__ void __launch_bounds__(256) split_w_kernel(
    const float* __restrict__ q_w, const float* __restrict__ k_w,
    const float* __restrict__ p_w)
{
    int idx = blockIdx.x * 256 + threadIdx.x;
    if (idx >= C_ * C_) return;
    const float* ws[3] = {q_w, k_w, p_w};
    #pragma unroll
    for (int br = 0; br < 3; ++br) {
        __half h1, h2s;
        split2(ws[br][idx], h1, h2s);
        g_wsplit[(br * 2 + 0) * C_ * C_ + idx] = h1;
        g_wsplit[(br * 2 + 1) * C_ * C_ + idx] = h2s;
    }
}

// x [batch][c][n] -> xsplit [batch][part][n][c]
__global__ void __launch_bounds__(256) split_x_kernel(const float* __restrict__ x)
{
    __shared__ float t[32][129];
    const int nb = blockIdx.x * 128;
    const int cb = blockIdx.y * 32;
    const int batch = blockIdx.z;
    const int tid = threadIdx.x;

    const float* xb = x + ((size_t)batch * C_ + cb) * N_ + nb;
    #pragma unroll
    for (int i = 0; i < 16; ++i) {
        int idx = tid + i * 256;
        int c = idx >> 7, n = idx & 127;
        t[c][n] = xb[(size_t)c * N_ + n];
    }
    __syncthreads();
    size_t ob = ((size_t)batch * 2) * N_ * C_ + (size_t)nb * C_ + cb;
    #pragma unroll
    for (int i = 0; i < 16; ++i) {
        int idx = tid + i * 256;
        int n = idx >> 5, c = idx & 31;
        __half h1, h2s;
        split2(t[c][n], h1, h2s);
        size_t o = ob + (size_t)n * C_ + c;
        g_xsplit[o] = h1;
        g_xsplit[o + (size_t)N_ * C_] = h2s;
    }
}

// ---------------------------------------------------------------------------
// K1: Q/K GEMM via mma.sync fp16 2-split Horner, 3 segments (rs term dropped:
// O(2^-22) relative, below existing fp32 accumulation noise) + BN.
// Segment order: (a1,b2),(a2,b1) ->*2^-11-> (a1,b1).
// CTA: 128x128, 4 warps of 64x64, grid (8, 4, 128), single-barrier 2-stage.
// minblocks=3: cap regs ~170 -> 3 CTAs/SM for better latency overlap.
// ---------------------------------------------------------------------------
__global__ void __launch_bounds__(128, 3) hmma_qk_kernel(
    const float* __restrict__ q_g, const float* __restrict__ q_be,
    const float* __restrict__ q_m, const float* __restrict__ q_v,
    const float* __restrict__ k_g, const float* __restrict__ k_be,
    const float* __restrict__ k_m, const float* __restrict__ k_v)
{
    __shared__ __half As[2][128][40];   // 32 cols + 16B pad
    __shared__ __half Bs[2][128][40];

    const int tid    = threadIdx.x;
    const int lane   = tid & 31;
    const int wid    = tid >> 5;
    const int warp_m = wid >> 1;     // 0..1
    const int warp_n = wid & 1;      // 0..1
    const int ntile  = blockIdx.x;
    const int branch = blockIdx.y >> 1;
    const int mhalf  = blockIdx.y & 1;
    const int batch  = blockIdx.z;

    const __half* Ab = g_wsplit + ((size_t)(branch * 2) * C_ + mhalf * 128) * C_;
    const __half* Bb = g_xsplit + ((size_t)(batch * 2) * N_ + ntile * 128) * C_;

    auto load_tiles = [&](int buf, int seg, int kc) {
        // seg0=(a1,b2) seg1=(a2,b1) seg2=(a1,b1)
        const int ap = (seg == 1) ? 1 : 0;
        const int bp = (seg == 0) ? 1 : 0;
        const __half* Ag = Ab + (size_t)ap * C_ * C_ + kc * 32;
        const __half* Bg = Bb + (size_t)bp * N_ * C_ + kc * 32;
        #pragma unroll
        for (int i = 0; i < 4; ++i) {
            int cid = tid + i * 128;
            int row = cid >> 2, c8 = (cid & 3) * 8;
            cpa16(smem_u32(&As[buf][row][c8]), Ag + (size_t)row * C_ + c8);
            cpa16(smem_u32(&Bs[buf][row][c8]), Bg + (size_t)row * C_ + c8);
        }
    };

    float acc[4][8][4];
    #pragma unroll
    for (int mt = 0; mt < 4; ++mt)
        #pragma unroll
        for (int nt = 0; nt < 8; ++nt)
            #pragma unroll
            for (int c = 0; c < 4; ++c)
                acc[mt][nt][c] = 0.0f;

    load_tiles(0, 0, 0);
    CP_COMMIT();

    #pragma unroll 1
    for (int it = 0; it < 24; ++it) {
        const int buf = it & 1;
        CP_WAIT0();
        __syncthreads();
        if (it < 23) {
            load_tiles(buf ^ 1, (it + 1) >> 3, (it + 1) & 7);
            CP_COMMIT();
        }

        #pragma unroll
        for (int ks = 0; ks < 2; ++ks) {
            uint32_t af[4][4];
            #pragma unroll
            for (int mt = 0; mt < 4; ++mt) {
                int arow = warp_m * 64 + mt * 16 + (lane & 15);
                int acol = ks * 16 + (lane >> 4) * 8;
                ldsm_x4(af[mt][0], af[mt][1], af[mt][2], af[mt][3],
                        smem_u32(&As[buf][arow][acol]));
            }
            uint32_t bfr[8][2];
            #pragma unroll
            for (int g = 0; g < 4; ++g) {
                int brow = warp_n * 64 + g * 16 + (lane & 7) + ((lane >> 4) & 1) * 8;
                int bcol = ks * 16 + ((lane >> 3) & 1) * 8;
                uint32_t r0, r1, r2, r3;
                ldsm_x4(r0, r1, r2, r3, smem_u32(&Bs[buf][brow][bcol]));
                bfr[g * 2 + 0][0] = r0;  bfr[g * 2 + 0][1] = r1;
                bfr[g * 2 + 1][0] = r2;  bfr[g * 2 + 1][1] = r3;
            }
            #pragma unroll
            for (int mt = 0; mt < 4; ++mt)
                #pragma unroll
                for (int nt = 0; nt < 8; ++nt)
                    mma_fp16(acc[mt][nt], af[mt], bfr[nt]);
        }

        // Horner rescale (exact power-of-2) after the two scaled segments
        if (it == 15) {
            #pragma unroll
            for (int mt = 0; mt < 4; ++mt)
                #pragma unroll
                for (int nt = 0; nt < 8; ++nt)
                    #pragma unroll
                    for (int c = 0; c < 4; ++c)
                        acc[mt][nt][c] *= SC_DOWN;
        }
    }

    // epilogue: BN and store
    const float* gg = branch ? k_g  : q_g;
    const float* vv = branch ? k_v  : q_v;
    const float* bb = branch ? k_be : q_be;
    const float* mm = branch ? k_m  : q_m;
    float* outp = branch ? g_klin : g_qlin;

    const int n0 = ntile * 128 + warp_n * 64 + (lane & 3) * 2;
    #pragma unroll
    for (int mt = 0; mt < 4; ++mt) {
        #pragma unroll
        for (int h = 0; h < 2; ++h) {
            const int o = mhalf * 128 + warp_m * 64 + mt * 16 + (lane >> 2) + h * 8;
            const float iv = gg[o] / sqrtf(vv[o] + EPS_);
            const float sh = bb[o] - mm[o] * iv;
            float* orow = outp + ((size_t)batch * C_ + o) * N_;
            #pragma unroll
            for (int nt = 0; nt < 8; ++nt) {
                float2 r;
                r.x = acc[mt][nt][h * 2 + 0] * iv + sh;
                r.y = acc[mt][nt][h * 2 + 1] * iv + sh;
                *(float2*)(orow + n0 + nt * 8) = r;
            }
        }
    }
}

// ---------------------------------------------------------------------------
// K2: fused q-LIF, k-LIF, head channel-sum, attn-LIF (v_th=0.5), gating.
// 16 channels per thread (half-head); lane-bit-4 pairs combine qsum via
// shfl_xor. grid (N/128=8, heads=8, B=32), 256 threads.
// ---------------------------------------------------------------------------
__global__ void __launch_bounds__(256) lif_attn_kernel()
{
    const int lane = threadIdx.x & 31;
    const int wrp  = threadIdx.x >> 5;          // 0..7
    const int nlo  = lane & 15;
    const int half = lane >> 4;                 // 0 or 1
    const int n = blockIdx.x * 128 + wrp * 16 + nlo;
    const int h = blockIdx.y;
    const int b = blockIdx.z;
    const int cbase = h * 32 + half * 16;

    float vq[16], vk[16];
    #pragma unroll
    for (int d = 0; d < 16; ++d) { vq[d] = 0.0f; vk[d] = 0.0f; }
    float va = 0.0f;

    #pragma unroll
    for (int t = 0; t < T_; ++t) {
        size_t base = ((size_t)(t * B_ + b) * C_ + cbase) * N_ + n;
        float qs = 0.0f;
        unsigned kmask = 0u;
        #pragma unroll
        for (int d = 0; d < 16; ++d) {
            float q  = g_qlin[base + (size_t)d * N_];
            float v1 = vq[d] + (q - vq[d]) * 0.5f;
            bool  sq = (v1 >= 1.0f);
            qs += sq ? 1.0f : 0.0f;
            vq[d] = sq ? 0.0f : v1;

            float kx = g_klin[base + (size_t)d * N_];
            float v2 = vk[d] + (kx - vk[d]) * 0.5f;
            bool  sk = (v2 >= 1.0f);
            if (sk) kmask |= (1u << d);
            vk[d] = sk ? 0.0f : v2;
        }
        // combine half-head sums; both pair threads get identical qs_tot
        float qs_tot = qs + __shfl_xor_sync(0xFFFFFFFFu, qs, 16);
        float va1 = va + (qs_tot - va) * 0.5f;
        bool  sa  = (va1 >= 0.5f);
        va = sa ? 0.0f : va1;

        unsigned one = sa ? 0x3C00u : 0u;   // fp16 1.0
        unsigned words[8];
        #pragma unroll
        for (int dp = 0; dp < 8; ++dp) {
            unsigned lo = ((kmask >> (2 * dp)) & 1u) ? one : 0u;
            unsigned hi = ((kmask >> (2 * dp + 1)) & 1u) ? one : 0u;
            words[dp] = lo | (hi << 16);
        }
        __half* dst = g_xoneT + ((size_t)(t * B_ + b) * N_ + n) * C_ + cbase;
        *(uint4*)(dst + 0) = make_uint4(words[0], words[1], words[2], words[3]);
        *(uint4*)(dst + 8) = make_uint4(words[4], words[5], words[6], words[7]);
    }
}

// ---------------------------------------------------------------------------
// K3: projection GEMM, fp16 2-split Horner (2 segments: h2s then h1; binary
// B exact). +bias +BN folded. Writes plin (= g_qlin reuse).
// grid (8, 2, 128), 128 threads, single-barrier 2-stage, minblocks=3.
// ---------------------------------------------------------------------------
__global__ void __launch_bounds__(128, 3) hmma_p_kernel(
    const float* __restrict__ p_b, const float* __restrict__ p_g,
    const float* __restrict__ p_be, const float* __restrict__ p_m,
    const float* __restrict__ p_v)
{
    __shared__ __half As[2][128][40];
    __shared__ __half Bs[2][128][40];

    const int tid    = threadIdx.x;
    const int lane   = tid & 31;
    const int wid    = tid >> 5;
    const int warp_m = wid >> 1;
    const int warp_n = wid & 1;
    const int ntile  = blockIdx.x;
    const int mhalf  = blockIdx.y;
    const int batch  = blockIdx.z;

    const __half* Ab = g_wsplit + ((size_t)(2 * 2) * C_ + mhalf * 128) * C_;
    const __half* Bb = g_xoneT + ((size_t)batch * N_ + ntile * 128) * C_;

    auto load_tiles = [&](int buf, int seg, int kc) {
        // Horner order: seg0 = h2s (part1), seg1 = h1 (part0)
        const __half* Ag = Ab + (size_t)(1 - seg) * C_ * C_ + kc * 32;
        const __half* Bg = Bb + kc * 32;
        #pragma unroll
        for (int i = 0; i < 4; ++i) {
            int cid = tid + i * 128;
            int row = cid >> 2, c8 = (cid & 3) * 8;
            cpa16(smem_u32(&As[buf][row][c8]), Ag + (size_t)row * C_ + c8);
            cpa16(smem_u32(&Bs[buf][row][c8]), Bg + (size_t)row * C_ + c8);
        }
    };

    float acc[4][8][4];
    #pragma unroll
    for (int mt = 0; mt < 4; ++mt)
        #pragma unroll
        for (int nt = 0; nt < 8; ++nt)
            #pragma unroll
            for (int c = 0; c < 4; ++c)
                acc[mt][nt][c] = 0.0f;

    load_tiles(0, 0, 0);
    CP_COMMIT();

    #pragma unroll 1
    for (int it = 0; it < 16; ++it) {
        const int buf = it & 1;
        CP_WAIT0();
        __syncthreads();
        if (it < 15) {
            load_tiles(buf ^ 1, (it + 1) >> 3, (it + 1) & 7);
            CP_COMMIT();
        }

        #pragma unroll
        for (int ks = 0; ks < 2; ++ks) {
            uint32_t af[4][4];
            #pragma unroll
            for (int mt = 0; mt < 4; ++mt) {
                int arow = warp_m * 64 + mt * 16 + (lane & 15);
                int acol = ks * 16 + (lane >> 4) * 8;
                ldsm_x4(af[mt][0], af[mt][1], af[mt][2], af[mt][3],
                        smem_u32(&As[buf][arow][acol]));
            }
            uint32_t bfr[8][2];
            #pragma unroll
            for (int g = 0; g < 4; ++g) {
                int brow = warp_n * 64 + g * 16 + (lane & 7) + ((lane >> 4) & 1) * 8;
                int bcol = ks * 16 + ((lane >> 3) & 1) * 8;
                uint32_t r0, r1, r2, r3;
                ldsm_x4(r0, r1, r2, r3, smem_u32(&Bs[buf][brow][bcol]));
                bfr[g * 2 + 0][0] = r0;  bfr[g * 2 + 0][1] = r1;
                bfr[g * 2 + 1][0] = r2;  bfr[g * 2 + 1][1] = r3;
            }
            #pragma unroll
            for (int mt = 0; mt < 4; ++mt)
                #pragma unroll
                for (int nt = 0; nt < 8; ++nt)
                    mma_fp16(acc[mt][nt], af[mt], bfr[nt]);
        }

        if (it == 7) {
            #pragma unroll
            for (int mt = 0; mt < 4; ++mt)
                #pragma unroll
                for (int nt = 0; nt < 8; ++nt)
                    #pragma unroll
                    for (int c = 0; c < 4; ++c)
                        acc[mt][nt][c] *= SC_DOWN;
        }
    }

    // epilogue: (y + bias)*inv + sh = y*inv + (bias*inv + sh); store plin
    const int n0 = ntile * 128 + warp_n * 64 + (lane & 3) * 2;
    #pragma unroll
    for (int mt = 0; mt < 4; ++mt) {
        #pragma unroll
        for (int h = 0; h < 2; ++h) {
            const int o = mhalf * 128 + warp_m * 64 + mt * 16 + (lane >> 2) + h * 8;
            const float iv = p_g[o] / sqrtf(p_v[o] + EPS_);
            const float sh = (p_be[o] - p_m[o] * iv) + p_b[o] * iv;
            float* orow = g_qlin + ((size_t)batch * C_ + o) * N_;
            #pragma unroll
            for (int nt = 0; nt < 8; ++nt) {
                float2 r;
                r.x = acc[mt][nt][h * 2 + 0] * iv + sh;
                r.y = acc[mt][nt][h * 2 + 1] * iv + sh;
                *(float2*)(orow + n0 + nt * 8) = r;
            }
        }
    }
}

// ---------------------------------------------------------------------------
// K4: final LIF over T (streaming, float4 per thread).
// ---------------------------------------------------------------------------
__global__ void __launch_bounds__(256) lif_out_kernel(float* __restrict__ out)
{
    const size_t i = ((size_t)blockIdx.x * 256 + threadIdx.x) * 4;
    const size_t stride = (size_t)B_ * C_ * N_;
    float4 v = make_float4(0.f, 0.f, 0.f, 0.f);
    #pragma unroll
    for (int t = 0; t < T_; ++t) {
        float4 y = *(const float4*)(g_qlin + (size_t)t * stride + i);
        float4 s;
        float v1;
        v1 = v.x + (y.x - v.x) * 0.5f; s.x = (v1 >= 1.0f) ? 1.0f : 0.0f; v.x = (v1 >= 1.0f) ? 0.0f : v1;
        v1 = v.y + (y.y - v.y) * 0.5f; s.y = (v1 >= 1.0f) ? 1.0f : 0.0f; v.y = (v1 >= 1.0f) ? 0.0f : v1;
        v1 = v.z + (y.z - v.z) * 0.5f; s.z = (v1 >= 1.0f) ? 1.0f : 0.0f; v.z = (v1 >= 1.0f) ? 0.0f : v1;
        v1 = v.w + (y.w - v.w) * 0.5f; s.w = (v1 >= 1.0f) ? 1.0f : 0.0f; v.w = (v1 >= 1.0f) ? 0.0f : v1;
        *(float4*)(out + (size_t)t * stride + i) = s;
    }
}

// ---------------------------------------------------------------------------
extern "C" void kernel_launch(void* const* d_in, const int* in_sizes, int n_in,
                              void* d_out, int out_size)
{
    (void)in_sizes; (void)n_in; (void)out_size;
    const float* x    = (const float*)d_in[0];
    const float* q_w  = (const float*)d_in[1];
    const float* q_g  = (const float*)d_in[2];
    const float* q_be = (const float*)d_in[3];
    const float* q_m  = (const float*)d_in[4];
    const float* q_v  = (const float*)d_in[5];
    const float* k_w  = (const float*)d_in[6];
    const float* k_g  = (const float*)d_in[7];
    const float* k_be = (const float*)d_in[8];
    const float* k_m  = (const float*)d_in[9];
    const float* k_v  = (const float*)d_in[10];
    const float* p_w  = (const float*)d_in[11];
    const float* p_b  = (const float*)d_in[12];
    const float* p_g  = (const float*)d_in[13];
    const float* p_be = (const float*)d_in[14];
    const float* p_m  = (const float*)d_in[15];
    const float* p_v  = (const float*)d_in[16];
    float* out = (float*)d_out;

    split_w_kernel<<<256, 256>>>(q_w, k_w, p_w);

    dim3 gs(N_ / 128, C_ / 32, NBATCH);
    split_x_kernel<<<gs, 256>>>(x);

    dim3 g1(8, 4, NBATCH);
    hmma_qk_kernel<<<g1, 128>>>(q_g, q_be, q_m, q_v, k_g, k_be, k_m, k_v);

    dim3 g2(N_ / 128, 8, B_);
    lif_attn_kernel<<<g2, 256>>>();

    dim3 g3(8, 2, NBATCH);
    hmma_p_kernel<<<g3, 128>>>(p_b, p_g, p_be, p_m, p_v);

    lif_out_kernel<<<(B_ * C_ * N_) / 4 / 256, 256>>>(out);
}

// round 16
// speedup vs baseline: 1.0275x; 1.0275x over previous
#include <cuda_runtime.h>
#include <cuda_fp16.h>
#include <math.h>
#include <cstdint>

// Problem dims
#define T_  4
#define B_  32
#define C_  256
#define N_  1024     // H*W
#define EPS_ 1e-5f
#define NBATCH (T_ * B_)   // 128

#define SC_DOWN 4.8828125e-4f   // 2^-11, exact

// Scratch (allocation-free rule: __device__ globals)
__device__ float g_qlin[NBATCH * C_ * N_];                  // also reused as plin
__device__ float g_klin[NBATCH * C_ * N_];
__device__ __half g_xsplit[(size_t)NBATCH * 2 * C_ * N_];   // [batch][part][c][n]
__device__ __half g_xoneT[(size_t)NBATCH * N_ * C_];        // [batch][n][c]
__device__ __half g_wsplit[3 * 2 * C_ * C_];                // [branch(q,k,p)][part][o][c]

// ---------------- PTX helpers (family-agnostic, sm_80+) ----------------
__device__ __forceinline__ uint32_t smem_u32(const void* p) {
    uint32_t a;
    asm("{ .reg .u64 t; cvta.to.shared.u64 t, %1; cvt.u32.u64 %0, t; }" : "=r"(a) : "l"(p));
    return a;
}
__device__ __forceinline__ void ldsm_x4(uint32_t& r0, uint32_t& r1, uint32_t& r2,
                                        uint32_t& r3, uint32_t addr) {
    asm volatile("ldmatrix.sync.aligned.m8n8.x4.shared.b16 {%0,%1,%2,%3}, [%4];"
                 : "=r"(r0), "=r"(r1), "=r"(r2), "=r"(r3) : "r"(addr));
}
__device__ __forceinline__ void ldsm_x4_t(uint32_t& r0, uint32_t& r1, uint32_t& r2,
                                          uint32_t& r3, uint32_t addr) {
    asm volatile("ldmatrix.sync.aligned.m8n8.x4.trans.shared.b16 {%0,%1,%2,%3}, [%4];"
                 : "=r"(r0), "=r"(r1), "=r"(r2), "=r"(r3) : "r"(addr));
}
__device__ __forceinline__ void mma_fp16(float* d, const uint32_t* a, const uint32_t* b) {
    asm volatile("mma.sync.aligned.m16n8k16.row.col.f32.f16.f16.f32 "
                 "{%0,%1,%2,%3}, {%4,%5,%6,%7}, {%8,%9}, {%0,%1,%2,%3};"
                 : "+f"(d[0]), "+f"(d[1]), "+f"(d[2]), "+f"(d[3])
                 : "r"(a[0]), "r"(a[1]), "r"(a[2]), "r"(a[3]), "r"(b[0]), "r"(b[1]));
}
__device__ __forceinline__ void cpa16(uint32_t saddr, const void* g) {
    asm volatile("cp.async.cg.shared.global [%0], [%1], 16;" :: "r"(saddr), "l"(g) : "memory");
}
#define CP_COMMIT() asm volatile("cp.async.commit_group;" ::: "memory")
#define CP_WAIT0()  asm volatile("cp.async.wait_group 0;" ::: "memory")

// ---------------------------------------------------------------------------
// Split: fp32 -> 2x fp16, second limb pre-scaled by 2^11 (exact) so both
// limbs live in fp16 normal range. x = h1 + 2^-11 * h2s  (+ O(2^-22 x)).
// ---------------------------------------------------------------------------
__device__ __forceinline__ void split2(float v, __half& h1, __half& h2s) {
    h1 = __float2half_rn(v);
    float r = v - __half2float(h1);        // Sterbenz-exact
    h2s = __float2half_rn(r * 2048.0f);    // exact scaling
}

__global__ void __launch_bounds__(256) split_w_kernel(
    const float* __restrict__ q_w, const float* __restrict__ k_w,
    const float* __restrict__ p_w)
{
    int idx = blockIdx.x * 256 + threadIdx.x;
    if (idx >= C_ * C_) return;
    const float* ws[3] = {q_w, k_w, p_w};
    #pragma unroll
    for (int br = 0; br < 3; ++br) {
        __half h1, h2s;
        split2(ws[br][idx], h1, h2s);
        g_wsplit[(br * 2 + 0) * C_ * C_ + idx] = h1;
        g_wsplit[(br * 2 + 1) * C_ * C_ + idx] = h2s;
    }
}

// x [batch][c][n] -> xsplit [batch][part][c][n]  (pure streaming, no transpose)
// 8 elements per thread: 2x float4 reads, 2x uint4 writes per part.
__global__ void __launch_bounds__(256) split_x_kernel(const float* __restrict__ x)
{
    const size_t e0 = ((size_t)blockIdx.x * 256 + threadIdx.x) * 8;
    const size_t cn = (size_t)C_ * N_;
    const size_t batch = e0 / cn;
    const size_t rem   = e0 - batch * cn;    // 8-aligned, stays within batch (cn % 8 == 0)

    float4 v0 = *(const float4*)(x + e0);
    float4 v1 = *(const float4*)(x + e0 + 4);
    __half h1[8], h2[8];
    const float vv[8] = {v0.x, v0.y, v0.z, v0.w, v1.x, v1.y, v1.z, v1.w};
    #pragma unroll
    for (int i = 0; i < 8; ++i) split2(vv[i], h1[i], h2[i]);

    __half* d1 = g_xsplit + (batch * 2) * cn + rem;          // part 0
    __half* d2 = d1 + cn;                                    // part 1
    *(uint4*)d1 = *(uint4*)h1;
    *(uint4*)d2 = *(uint4*)h2;
}

// ---------------------------------------------------------------------------
// K1: Q/K GEMM via mma.sync fp16 2-split Horner, 3 segments + BN.
// Segment order: (a1,b2),(a2,b1) ->*2^-11-> (a1,b1).
// CTA: 128x128, 4 warps of 64x64, grid (8, 4, 128), single-barrier 2-stage.
// B operand kept in natural [k][n] layout; fragments via ldmatrix.trans.
// ---------------------------------------------------------------------------
__global__ void __launch_bounds__(128) hmma_qk_kernel(
    const float* __restrict__ q_g, const float* __restrict__ q_be,
    const float* __restrict__ q_m, const float* __restrict__ q_v,
    const float* __restrict__ k_g, const float* __restrict__ k_be,
    const float* __restrict__ k_m, const float* __restrict__ k_v)
{
    __shared__ __half As[2][128][40];   // [m][k] 32 cols + pad
    __shared__ __half Bs[2][32][136];   // [k][n] 128 cols + 8 pad (272B row)

    const int tid    = threadIdx.x;
    const int lane   = tid & 31;
    const int wid    = tid >> 5;
    const int warp_m = wid >> 1;     // 0..1
    const int warp_n = wid & 1;      // 0..1
    const int ntile  = blockIdx.x;
    const int branch = blockIdx.y >> 1;
    const int mhalf  = blockIdx.y & 1;
    const int batch  = blockIdx.z;

    const __half* Ab = g_wsplit + ((size_t)(branch * 2) * C_ + mhalf * 128) * C_;
    const __half* Bb = g_xsplit + (size_t)(batch * 2) * C_ * N_ + ntile * 128;

    auto load_tiles = [&](int buf, int seg, int kc) {
        // seg0=(a1,b2) seg1=(a2,b1) seg2=(a1,b1)
        const int ap = (seg == 1) ? 1 : 0;
        const int bp = (seg == 0) ? 1 : 0;
        const __half* Ag = Ab + (size_t)ap * C_ * C_ + kc * 32;
        const __half* Bg = Bb + (size_t)bp * C_ * N_ + (size_t)(kc * 32) * N_;
        #pragma unroll
        for (int i = 0; i < 4; ++i) {
            int cid = tid + i * 128;
            {   // A: 128 rows x 64B
                int row = cid >> 2, c8 = (cid & 3) * 8;
                cpa16(smem_u32(&As[buf][row][c8]), Ag + (size_t)row * C_ + c8);
            }
            {   // B: 32 k-rows x 256B
                int row = cid >> 4, n8 = (cid & 15) * 8;
                cpa16(smem_u32(&Bs[buf][row][n8]), Bg + (size_t)row * N_ + n8);
            }
        }
    };

    float acc[4][8][4];
    #pragma unroll
    for (int mt = 0; mt < 4; ++mt)
        #pragma unroll
        for (int nt = 0; nt < 8; ++nt)
            #pragma unroll
            for (int c = 0; c < 4; ++c)
                acc[mt][nt][c] = 0.0f;

    load_tiles(0, 0, 0);
    CP_COMMIT();

    const int grp = lane >> 3;      // 0..3: which 8x8 matrix this lane addresses
    const int rr  = lane & 7;

    #pragma unroll 1
    for (int it = 0; it < 24; ++it) {
        const int buf = it & 1;
        CP_WAIT0();
        __syncthreads();
        if (it < 23) {
            load_tiles(buf ^ 1, (it + 1) >> 3, (it + 1) & 7);
            CP_COMMIT();
        }

        #pragma unroll
        for (int ks = 0; ks < 2; ++ks) {
            uint32_t af[4][4];
            #pragma unroll
            for (int mt = 0; mt < 4; ++mt) {
                int arow = warp_m * 64 + mt * 16 + (lane & 15);
                int acol = ks * 16 + (lane >> 4) * 8;
                ldsm_x4(af[mt][0], af[mt][1], af[mt][2], af[mt][3],
                        smem_u32(&As[buf][arow][acol]));
            }
            uint32_t bfr[8][2];
            // trans-load: matrices m0..m3 = (k0-7,n8a),(k8-15,n8a),(k0-7,n8b),(k8-15,n8b)
            const int krow = ks * 16 + (grp & 1) * 8 + rr;
            #pragma unroll
            for (int g = 0; g < 4; ++g) {
                int ncol = warp_n * 64 + g * 16 + (grp >> 1) * 8;
                uint32_t r0, r1, r2, r3;
                ldsm_x4_t(r0, r1, r2, r3, smem_u32(&Bs[buf][krow][ncol]));
                bfr[g * 2 + 0][0] = r0;  bfr[g * 2 + 0][1] = r1;
                bfr[g * 2 + 1][0] = r2;  bfr[g * 2 + 1][1] = r3;
            }
            #pragma unroll
            for (int mt = 0; mt < 4; ++mt)
                #pragma unroll
                for (int nt = 0; nt < 8; ++nt)
                    mma_fp16(acc[mt][nt], af[mt], bfr[nt]);
        }

        // Horner rescale (exact power-of-2) after the two scaled segments
        if (it == 15) {
            #pragma unroll
            for (int mt = 0; mt < 4; ++mt)
                #pragma unroll
                for (int nt = 0; nt < 8; ++nt)
                    #pragma unroll
                    for (int c = 0; c < 4; ++c)
                        acc[mt][nt][c] *= SC_DOWN;
        }
    }

    // epilogue: BN and store
    const float* gg = branch ? k_g  : q_g;
    const float* vv = branch ? k_v  : q_v;
    const float* bb = branch ? k_be : q_be;
    const float* mm = branch ? k_m  : q_m;
    float* outp = branch ? g_klin : g_qlin;

    const int n0 = ntile * 128 + warp_n * 64 + (lane & 3) * 2;
    #pragma unroll
    for (int mt = 0; mt < 4; ++mt) {
        #pragma unroll
        for (int h = 0; h < 2; ++h) {
            const int o = mhalf * 128 + warp_m * 64 + mt * 16 + (lane >> 2) + h * 8;
            const float iv = gg[o] / sqrtf(vv[o] + EPS_);
            const float sh = bb[o] - mm[o] * iv;
            float* orow = outp + ((size_t)batch * C_ + o) * N_;
            #pragma unroll
            for (int nt = 0; nt < 8; ++nt) {
                float2 r;
                r.x = acc[mt][nt][h * 2 + 0] * iv + sh;
                r.y = acc[mt][nt][h * 2 + 1] * iv + sh;
                *(float2*)(orow + n0 + nt * 8) = r;
            }
        }
    }
}

// ---------------------------------------------------------------------------
// K2: fused q-LIF, k-LIF, head channel-sum, attn-LIF (v_th=0.5), gating.
// 16 channels per thread (half-head); lane-bit-4 pairs combine qsum via
// shfl_xor. grid (N/128=8, heads=8, B=32), 256 threads.
// ---------------------------------------------------------------------------
__global__ void __launch_bounds__(256) lif_attn_kernel()
{
    const int lane = threadIdx.x & 31;
    const int wrp  = threadIdx.x >> 5;          // 0..7
    const int nlo  = lane & 15;
    const int half = lane >> 4;                 // 0 or 1
    const int n = blockIdx.x * 128 + wrp * 16 + nlo;
    const int h = blockIdx.y;
    const int b = blockIdx.z;
    const int cbase = h * 32 + half * 16;

    float vq[16], vk[16];
    #pragma unroll
    for (int d = 0; d < 16; ++d) { vq[d] = 0.0f; vk[d] = 0.0f; }
    float va = 0.0f;

    #pragma unroll
    for (int t = 0; t < T_; ++t) {
        size_t base = ((size_t)(t * B_ + b) * C_ + cbase) * N_ + n;
        float qs = 0.0f;
        unsigned kmask = 0u;
        #pragma unroll
        for (int d = 0; d < 16; ++d) {
            float q  = g_qlin[base + (size_t)d * N_];
            float v1 = vq[d] + (q - vq[d]) * 0.5f;
            bool  sq = (v1 >= 1.0f);
            qs += sq ? 1.0f : 0.0f;
            vq[d] = sq ? 0.0f : v1;

            float kx = g_klin[base + (size_t)d * N_];
            float v2 = vk[d] + (kx - vk[d]) * 0.5f;
            bool  sk = (v2 >= 1.0f);
            if (sk) kmask |= (1u << d);
            vk[d] = sk ? 0.0f : v2;
        }
        // combine half-head sums; both pair threads get identical qs_tot
        float qs_tot = qs + __shfl_xor_sync(0xFFFFFFFFu, qs, 16);
        float va1 = va + (qs_tot - va) * 0.5f;
        bool  sa  = (va1 >= 0.5f);
        va = sa ? 0.0f : va1;

        unsigned one = sa ? 0x3C00u : 0u;   // fp16 1.0
        unsigned words[8];
        #pragma unroll
        for (int dp = 0; dp < 8; ++dp) {
            unsigned lo = ((kmask >> (2 * dp)) & 1u) ? one : 0u;
            unsigned hi = ((kmask >> (2 * dp + 1)) & 1u) ? one : 0u;
            words[dp] = lo | (hi << 16);
        }
        __half* dst = g_xoneT + ((size_t)(t * B_ + b) * N_ + n) * C_ + cbase;
        *(uint4*)(dst + 0) = make_uint4(words[0], words[1], words[2], words[3]);
        *(uint4*)(dst + 8) = make_uint4(words[4], words[5], words[6], words[7]);
    }
}

// ---------------------------------------------------------------------------
// K3: projection GEMM, fp16 2-split Horner (2 segments: h2s then h1; binary
// B exact). +bias +BN folded. Writes plin (= g_qlin reuse).
// grid (8, 2, 128), 128 threads, single-barrier 2-stage. (Unchanged R13.)
// ---------------------------------------------------------------------------
__global__ void __launch_bounds__(128) hmma_p_kernel(
    const float* __restrict__ p_b, const float* __restrict__ p_g,
    const float* __restrict__ p_be, const float* __restrict__ p_m,
    const float* __restrict__ p_v)
{
    __shared__ __half As[2][128][40];
    __shared__ __half Bs[2][128][40];

    const int tid    = threadIdx.x;
    const int lane   = tid & 31;
    const int wid    = tid >> 5;
    const int warp_m = wid >> 1;
    const int warp_n = wid & 1;
    const int ntile  = blockIdx.x;
    const int mhalf  = blockIdx.y;
    const int batch  = blockIdx.z;

    const __half* Ab = g_wsplit + ((size_t)(2 * 2) * C_ + mhalf * 128) * C_;
    const __half* Bb = g_xoneT + ((size_t)batch * N_ + ntile * 128) * C_;

    auto load_tiles = [&](int buf, int seg, int kc) {
        // Horner order: seg0 = h2s (part1), seg1 = h1 (part0)
        const __half* Ag = Ab + (size_t)(1 - seg) * C_ * C_ + kc * 32;
        const __half* Bg = Bb + kc * 32;
        #pragma unroll
        for (int i = 0; i < 4; ++i) {
            int cid = tid + i * 128;
            int row = cid >> 2, c8 = (cid & 3) * 8;
            cpa16(smem_u32(&As[buf][row][c8]), Ag + (size_t)row * C_ + c8);
            cpa16(smem_u32(&Bs[buf][row][c8]), Bg + (size_t)row * C_ + c8);
        }
    };

    float acc[4][8][4];
    #pragma unroll
    for (int mt = 0; mt < 4; ++mt)
        #pragma unroll
        for (int nt = 0; nt < 8; ++nt)
            #pragma unroll
            for (int c = 0; c < 4; ++c)
                acc[mt][nt][c] = 0.0f;

    load_tiles(0, 0, 0);
    CP_COMMIT();

    #pragma unroll 1
    for (int it = 0; it < 16; ++it) {
        const int buf = it & 1;
        CP_WAIT0();
        __syncthreads();
        if (it < 15) {
            load_tiles(buf ^ 1, (it + 1) >> 3, (it + 1) & 7);
            CP_COMMIT();
        }

        #pragma unroll
        for (int ks = 0; ks < 2; ++ks) {
            uint32_t af[4][4];
            #pragma unroll
            for (int mt = 0; mt < 4; ++mt) {
                int arow = warp_m * 64 + mt * 16 + (lane & 15);
                int acol = ks * 16 + (lane >> 4) * 8;
                ldsm_x4(af[mt][0], af[mt][1], af[mt][2], af[mt][3],
                        smem_u32(&As[buf][arow][acol]));
            }
            uint32_t bfr[8][2];
            #pragma unroll
            for (int g = 0; g < 4; ++g) {
                int brow = warp_n * 64 + g * 16 + (lane & 7) + ((lane >> 4) & 1) * 8;
                int bcol = ks * 16 + ((lane >> 3) & 1) * 8;
                uint32_t r0, r1, r2, r3;
                ldsm_x4(r0, r1, r2, r3, smem_u32(&Bs[buf][brow][bcol]));
                bfr[g * 2 + 0][0] = r0;  bfr[g * 2 + 0][1] = r1;
                bfr[g * 2 + 1][0] = r2;  bfr[g * 2 + 1][1] = r3;
            }
            #pragma unroll
            for (int mt = 0; mt < 4; ++mt)
                #pragma unroll
                for (int nt = 0; nt < 8; ++nt)
                    mma_fp16(acc[mt][nt], af[mt], bfr[nt]);
        }

        if (it == 7) {
            #pragma unroll
            for (int mt = 0; mt < 4; ++mt)
                #pragma unroll
                for (int nt = 0; nt < 8; ++nt)
                    #pragma unroll
                    for (int c = 0; c < 4; ++c)
                        acc[mt][nt][c] *= SC_DOWN;
        }
    }

    // epilogue: (y + bias)*inv + sh = y*inv + (bias*inv + sh); store plin
    const int n0 = ntile * 128 + warp_n * 64 + (lane & 3) * 2;
    #pragma unroll
    for (int mt = 0; mt < 4; ++mt) {
        #pragma unroll
        for (int h = 0; h < 2; ++h) {
            const int o = mhalf * 128 + warp_m * 64 + mt * 16 + (lane >> 2) + h * 8;
            const float iv = p_g[o] / sqrtf(p_v[o] + EPS_);
            const float sh = (p_be[o] - p_m[o] * iv) + p_b[o] * iv;
            float* orow = g_qlin + ((size_t)batch * C_ + o) * N_;
            #pragma unroll
            for (int nt = 0; nt < 8; ++nt) {
                float2 r;
                r.x = acc[mt][nt][h * 2 + 0] * iv + sh;
                r.y = acc[mt][nt][h * 2 + 1] * iv + sh;
                *(float2*)(orow + n0 + nt * 8) = r;
            }
        }
    }
}

// ---------------------------------------------------------------------------
// K4: final LIF over T (streaming, float4 per thread).
// ---------------------------------------------------------------------------
__global__ void __launch_bounds__(256) lif_out_kernel(float* __restrict__ out)
{
    const size_t i = ((size_t)blockIdx.x * 256 + threadIdx.x) * 4;
    const size_t stride = (size_t)B_ * C_ * N_;
    float4 v = make_float4(0.f, 0.f, 0.f, 0.f);
    #pragma unroll
    for (int t = 0; t < T_; ++t) {
        float4 y = *(const float4*)(g_qlin + (size_t)t * stride + i);
        float4 s;
        float v1;
        v1 = v.x + (y.x - v.x) * 0.5f; s.x = (v1 >= 1.0f) ? 1.0f : 0.0f; v.x = (v1 >= 1.0f) ? 0.0f : v1;
        v1 = v.y + (y.y - v.y) * 0.5f; s.y = (v1 >= 1.0f) ? 1.0f : 0.0f; v.y = (v1 >= 1.0f) ? 0.0f : v1;
        v1 = v.z + (y.z - v.z) * 0.5f; s.z = (v1 >= 1.0f) ? 1.0f : 0.0f; v.z = (v1 >= 1.0f) ? 0.0f : v1;
        v1 = v.w + (y.w - v.w) * 0.5f; s.w = (v1 >= 1.0f) ? 1.0f : 0.0f; v.w = (v1 >= 1.0f) ? 0.0f : v1;
        *(float4*)(out + (size_t)t * stride + i) = s;
    }
}

// ---------------------------------------------------------------------------
extern "C" void kernel_launch(void* const* d_in, const int* in_sizes, int n_in,
                              void* d_out, int out_size)
{
    (void)in_sizes; (void)n_in; (void)out_size;
    const float* x    = (const float*)d_in[0];
    const float* q_w  = (const float*)d_in[1];
    const float* q_g  = (const float*)d_in[2];
    const float* q_be = (const float*)d_in[3];
    const float* q_m  = (const float*)d_in[4];
    const float* q_v  = (const float*)d_in[5];
    const float* k_w  = (const float*)d_in[6];
    const float* k_g  = (const float*)d_in[7];
    const float* k_be = (const float*)d_in[8];
    const float* k_m  = (const float*)d_in[9];
    const float* k_v  = (const float*)d_in[10];
    const float* p_w  = (const float*)d_in[11];
    const float* p_b  = (const float*)d_in[12];
    const float* p_g  = (const float*)d_in[13];
    const float* p_be = (const float*)d_in[14];
    const float* p_m  = (const float*)d_in[15];
    const float* p_v  = (const float*)d_in[16];
    float* out = (float*)d_out;

    split_w_kernel<<<256, 256>>>(q_w, k_w, p_w);

    split_x_kernel<<<(NBATCH * C_ * N_) / 8 / 256, 256>>>(x);

    dim3 g1(8, 4, NBATCH);
    hmma_qk_kernel<<<g1, 128>>>(q_g, q_be, q_m, q_v, k_g, k_be, k_m, k_v);

    dim3 g2(N_ / 128, 8, B_);
    lif_attn_kernel<<<g2, 256>>>();

    dim3 g3(8, 2, NBATCH);
    hmma_p_kernel<<<g3, 128>>>(p_b, p_g, p_be, p_m, p_v);

    lif_out_kernel<<<(B_ * C_ * N_) / 4 / 256, 256>>>(out);
}